// round 15
// baseline (speedup 1.0000x reference)
#include <cuda_runtime.h>
#include <cstddef>

#define TT 1024
#define BB 32
#define NBLK 128
#define OUT1_ELEMS (TT*BB*512)
#define BH (BB*512)

#define WTS 20      // weight smem stride per k (16 rows + 4 pad) -> conflict-free
#define HSS 516     // h smem row stride (floats)
#define PSR 264     // psm row stride: 32 batches * 8 kh + 8 pad

// ---------------- device globals (scratch; no allocation allowed) ------------
__device__ float g_gi0[(size_t)TT * BB * 2048];
__device__ float g_h0buf[2 * BH];
__device__ float g_h1buf[2 * BH];
__device__ unsigned g_flags[NBLK * 64];   // one 256B slot per block, monotonic

// ======================= input-projection GEMM ===============================
__global__ void __launch_bounds__(256) gemm_in2h(
    const float* __restrict__ A, const float* __restrict__ W,
    const float* __restrict__ bias)
{
    __shared__ float As[8][132];
    __shared__ float Bs[8][132];
    const int tid = threadIdx.x;
    const int n0 = blockIdx.x * 128;
    const int m0 = blockIdx.y * 128;
    const int tx = tid & 15, ty = tid >> 4;
    const int lrow = tid >> 1, lk4 = (tid & 1) * 4;
    const float* Ab = A + (size_t)(m0 + lrow) * 512 + lk4;
    const float* Wb = W + (size_t)(n0 + lrow) * 512 + lk4;

    float acc[8][8];
#pragma unroll
    for (int i = 0; i < 8; i++)
#pragma unroll
        for (int j = 0; j < 8; j++) acc[i][j] = 0.f;

    for (int k0 = 0; k0 < 512; k0 += 8) {
        float4 av = *(const float4*)(Ab + k0);
        float4 wv = *(const float4*)(Wb + k0);
        As[lk4 + 0][lrow] = av.x; As[lk4 + 1][lrow] = av.y;
        As[lk4 + 2][lrow] = av.z; As[lk4 + 3][lrow] = av.w;
        Bs[lk4 + 0][lrow] = wv.x; Bs[lk4 + 1][lrow] = wv.y;
        Bs[lk4 + 2][lrow] = wv.z; Bs[lk4 + 3][lrow] = wv.w;
        __syncthreads();
#pragma unroll
        for (int k = 0; k < 8; k++) {
            float a[8], b[8];
            *(float4*)&a[0] = *(const float4*)&As[k][ty * 8];
            *(float4*)&a[4] = *(const float4*)&As[k][ty * 8 + 4];
            *(float4*)&b[0] = *(const float4*)&Bs[k][tx * 8];
            *(float4*)&b[4] = *(const float4*)&Bs[k][tx * 8 + 4];
#pragma unroll
            for (int i = 0; i < 8; i++)
#pragma unroll
                for (int j = 0; j < 8; j++) acc[i][j] += a[i] * b[j];
        }
        __syncthreads();
    }

    float bv[8];
#pragma unroll
    for (int j = 0; j < 8; j++) bv[j] = bias[n0 + tx * 8 + j];
#pragma unroll
    for (int i = 0; i < 8; i++) {
        size_t row = (size_t)(m0 + ty * 8 + i);
        float* Crow = g_gi0 + row * 2048 + n0 + tx * 8;
#pragma unroll
        for (int j = 0; j < 8; j++) Crow[j] = acc[i][j] + bv[j];
    }
}

// ======================= persistent recurrence kernel ========================
__device__ __forceinline__ float sigf(float x) {
    float e = __expf(fminf(-x, 80.f));
    return __fdividef(1.f, 1.f + e);
}
__device__ __forceinline__ float tanhfast(float x) {
    float e = __expf(fminf(2.f * x, 80.f));
    return 1.f - __fdividef(2.f, e + 1.f);
}

__device__ __forceinline__ unsigned long long fma2(unsigned long long a,
                                                   unsigned long long b,
                                                   unsigned long long c) {
    unsigned long long d;
    asm("fma.rn.f32x2 %0, %1, %2, %3;" : "=l"(d) : "l"(a), "l"(b), "l"(c));
    return d;
}
__device__ __forceinline__ unsigned long long addf2(unsigned long long a,
                                                    unsigned long long b) {
    unsigned long long d;
    asm("add.rn.f32x2 %0, %1, %2;" : "=l"(d) : "l"(a), "l"(b));
    return d;
}

// release/acquire flag barrier: per-block 256B slot, monotonic generation.
__device__ __forceinline__ void flagbar(unsigned gen, int tid) {
    __syncthreads();
    if (tid == 0) {
        asm volatile("st.release.gpu.u32 [%0], %1;"
                     :: "l"(&g_flags[blockIdx.x * 64]), "r"(gen) : "memory");
    }
    if (tid < NBLK) {
        unsigned v;
        do {
            asm volatile("ld.acquire.gpu.u32 %0, [%1];"
                         : "=r"(v) : "l"(&g_flags[tid * 64]) : "memory");
        } while (v < gen);
    }
    __syncthreads();
}

// L2-only copy: src [32][512] contiguous -> hs rows of stride HSS
__device__ __forceinline__ void stage_h(float* __restrict__ hs,
                                        const float* __restrict__ src, int tid) {
#pragma unroll
    for (int it = 0; it < 4; it++) {
        int u4 = tid + it * 1024;
        int b = u4 >> 7, k4 = (u4 & 127) << 2;
        float4 v = __ldcg(((const float4*)src) + u4);
        *(float4*)(hs + b * HSS + k4) = v;
    }
}

// warp: 2 batches/thread x 16 rows (8 f32x2 rowpairs) x 64 k
__device__ __forceinline__ void gemm_rp(const float* __restrict__ hs,
                                        const float* __restrict__ ws,
                                        int b0t, int kbase,
                                        unsigned long long acc[2][8]) {
    const float* hp = hs + b0t * HSS + kbase;
    const float* wp = ws + kbase * WTS;
#pragma unroll
    for (int m = 0; m < 8; m++) {
        float h0 = hp[m * 8];
        float h1 = hp[HSS + m * 8];
        unsigned long long H0, H1;
        asm("mov.b64 %0, {%1, %1};" : "=l"(H0) : "f"(h0));
        asm("mov.b64 %0, {%1, %1};" : "=l"(H1) : "f"(h1));
        const float* w = wp + m * 8 * WTS;
        ulonglong2 w01 = *(const ulonglong2*)(w);
        ulonglong2 w23 = *(const ulonglong2*)(w + 4);
        ulonglong2 w45 = *(const ulonglong2*)(w + 8);
        ulonglong2 w67 = *(const ulonglong2*)(w + 12);
        acc[0][0] = fma2(H0, w01.x, acc[0][0]); acc[1][0] = fma2(H1, w01.x, acc[1][0]);
        acc[0][1] = fma2(H0, w01.y, acc[0][1]); acc[1][1] = fma2(H1, w01.y, acc[1][1]);
        acc[0][2] = fma2(H0, w23.x, acc[0][2]); acc[1][2] = fma2(H1, w23.x, acc[1][2]);
        acc[0][3] = fma2(H0, w23.y, acc[0][3]); acc[1][3] = fma2(H1, w23.y, acc[1][3]);
        acc[0][4] = fma2(H0, w45.x, acc[0][4]); acc[1][4] = fma2(H1, w45.x, acc[1][4]);
        acc[0][5] = fma2(H0, w45.y, acc[0][5]); acc[1][5] = fma2(H1, w45.y, acc[1][5]);
        acc[0][6] = fma2(H0, w67.x, acc[0][6]); acc[1][6] = fma2(H1, w67.x, acc[1][6]);
        acc[0][7] = fma2(H0, w67.y, acc[0][7]); acc[1][7] = fma2(H1, w67.y, acc[1][7]);
    }
}

// reduce over the 8 kcl lanes; lane kcl writes rowpair j2 == kcl to psm[r][b][kh]
__device__ __forceinline__ void red_write_rp(unsigned long long acc[2][8],
                                             float* __restrict__ psm,
                                             int kh, int kcl, int b0t) {
#pragma unroll
    for (int j2 = 0; j2 < 8; j2++) {
#pragma unroll
        for (int b2 = 0; b2 < 2; b2++) {
            unsigned long long v = acc[b2][j2];
            v = addf2(v, __shfl_xor_sync(0xffffffffu, v, 1));
            v = addf2(v, __shfl_xor_sync(0xffffffffu, v, 2));
            v = addf2(v, __shfl_xor_sync(0xffffffffu, v, 4));
            acc[b2][j2] = v;
        }
        if (j2 == kcl) {
            float2 f0 = *(float2*)&acc[0][j2];
            float2 f1 = *(float2*)&acc[1][j2];
            psm[(2 * j2) * PSR     + b0t * 8       + kh] = f0.x;
            psm[(2 * j2 + 1) * PSR + b0t * 8       + kh] = f0.y;
            psm[(2 * j2) * PSR     + (b0t + 1) * 8 + kh] = f1.x;
            psm[(2 * j2 + 1) * PSR + (b0t + 1) * 8 + kh] = f1.y;
        }
    }
}

__global__ void __launch_bounds__(1024, 1) lstm_rec(
    const float* __restrict__ w_hh0, const float* __restrict__ b_hh0,
    const float* __restrict__ w_ih1, const float* __restrict__ w_hh1,
    const float* __restrict__ b_ih1, const float* __restrict__ b_hh1,
    const float* __restrict__ h0_in, const float* __restrict__ c0_in,
    float* __restrict__ dout)
{
    extern __shared__ float sm[];
    float* ws0   = sm;                    // 512*20 = 10240
    float* wsi1  = sm + 10240;
    float* wsh1  = sm + 20480;
    float* hs    = sm + 30720;            // 32*516 = 16512
    float* psmL0 = sm + 47232;            // 16*264 = 4224
    float* psmL1 = sm + 51456;            // 4224
    float* csm   = sm + 55680;            // 256
    float* bsm   = sm + 55936;            // 32 biases [L][g][jl]

    const int tid = threadIdx.x;
    const int bid = blockIdx.x;
    const int J0 = bid << 2;

    const unsigned gbase = *(volatile unsigned*)&g_flags[bid * 64];

    // Stage 16 weight rows per matrix, k-major [k][16 rows + pad], once.
    for (int u = tid; u < 16 * 512; u += 1024) {
        int r = u >> 9, k = u & 511;
        int gr = ((r >> 2) << 9) + J0 + (r & 3);
        int d = k * WTS + r;
        ws0[d]  = w_hh0[gr * 512 + k];
        wsi1[d] = w_ih1[gr * 512 + k];
        wsh1[d] = w_hh1[gr * 512 + k];
    }
    // init hidden buffers at parity 1
    if (tid < 512) {
        int g = (bid << 9) + tid;
        if (g < BH)          g_h0buf[BH + g] = h0_in[g];
        else if (g < 2 * BH) g_h1buf[g]      = h0_in[g];
    }
    if (tid < 256) {
        int l = tid >> 7, jl = (tid >> 5) & 3, b = tid & 31;
        csm[tid] = c0_in[(l << 14) + (b << 9) + J0 + jl];
    }
    // combined biases into smem: bsm[L*16 + g*4 + jl]
    if (tid < 32) {
        int L = tid >> 4, g = (tid >> 2) & 3, jl = tid & 3;
        int idx = g * 512 + J0 + jl;
        bsm[tid] = (L == 0) ? b_hh0[idx] : (b_ih1[idx] + b_hh1[idx]);
    }

    const int lane = tid & 31, warp = tid >> 5;
    const int bgrp = warp & 3, kh = warp >> 2;      // 4 batch grps x 8 k grps
    const int kcl = lane & 7, bsub = lane >> 3;
    const int b0t = bgrp * 8 + bsub * 2;            // 2 batches per thread
    const int kbase = kh * 64 + kcl;

    flagbar(gbase + 1, tid);

    unsigned long long acc[2][8];

    // pipelined: interval v computes L0 step v and L1 step v-1
    for (int v = 0; v <= TT; v++) {
        const int p0 = v & 1, q0 = p0 ^ 1;

        float giI = 0, giF = 0, giG = 0, giO = 0;
        if (v < TT && tid < 128) {
            int jl = tid >> 5, b = tid & 31, Jj = J0 + jl;
            const float* gi = g_gi0 + ((size_t)v << 16) + ((size_t)b << 11);
            giI = gi[Jj]; giF = gi[512 + Jj]; giG = gi[1024 + Jj]; giO = gi[1536 + Jj];
        }

        // ---- stage h0(v-1): shared by L0 w_hh0 and L1 w_ih1 ----
        stage_h(hs, g_h0buf + (q0 << 14), tid);
        __syncthreads();

        if (v < TT) {
#pragma unroll
            for (int i = 0; i < 2; i++)
#pragma unroll
                for (int j = 0; j < 8; j++) acc[i][j] = 0ull;
            gemm_rp(hs, ws0, b0t, kbase, acc);
            red_write_rp(acc, psmL0, kh, kcl, b0t);
        }
        if (v > 0) {
#pragma unroll
            for (int i = 0; i < 2; i++)
#pragma unroll
                for (int j = 0; j < 8; j++) acc[i][j] = 0ull;
            gemm_rp(hs, wsi1, b0t, kbase, acc);
        }
        __syncthreads();   // done reading hs

        if (v > 0) {
            stage_h(hs, g_h1buf + (p0 << 14), tid);  // h1(v-2)
            __syncthreads();
            gemm_rp(hs, wsh1, b0t, kbase, acc);      // accumulate
            red_write_rp(acc, psmL1, kh, kcl, b0t);
        }
        __syncthreads();   // psm ready

        // ---- L0 elementwise: step v ----
        if (v < TT && tid < 128) {
            int jl = tid >> 5, b = tid & 31, Jj = J0 + jl;
            const float* p = psmL0 + b * 8;
            float4 a0 = *(const float4*)(p + (jl) * PSR);
            float4 a1 = *(const float4*)(p + (jl) * PSR + 4);
            float4 f0 = *(const float4*)(p + (4 + jl) * PSR);
            float4 f1 = *(const float4*)(p + (4 + jl) * PSR + 4);
            float4 g0 = *(const float4*)(p + (8 + jl) * PSR);
            float4 g1 = *(const float4*)(p + (8 + jl) * PSR + 4);
            float4 o0 = *(const float4*)(p + (12 + jl) * PSR);
            float4 o1 = *(const float4*)(p + (12 + jl) * PSR + 4);
            float gI = giI + bsm[jl]      + a0.x + a0.y + a0.z + a0.w + a1.x + a1.y + a1.z + a1.w;
            float gF = giF + bsm[4 + jl]  + f0.x + f0.y + f0.z + f0.w + f1.x + f1.y + f1.z + f1.w;
            float gG = giG + bsm[8 + jl]  + g0.x + g0.y + g0.z + g0.w + g1.x + g1.y + g1.z + g1.w;
            float gO = giO + bsm[12 + jl] + o0.x + o0.y + o0.z + o0.w + o1.x + o1.y + o1.z + o1.w;
            float iv = sigf(gI), fv = sigf(gF), gv = tanhfast(gG), ov = sigf(gO);
            float c = fv * csm[jl * 32 + b] + iv * gv;
            csm[jl * 32 + b] = c;
            float h = ov * tanhfast(c);
            g_h0buf[(p0 << 14) + (b << 9) + Jj] = h;
            if (v == TT - 1) {
                dout[OUT1_ELEMS + (b << 9) + Jj] = h;
                dout[OUT1_ELEMS + 2 * BH + (b << 9) + Jj] = c;
            }
        }

        // ---- L1 elementwise: step v-1 ----
        if (v > 0 && tid >= 128 && tid < 256) {
            int lt = tid - 128;
            int jl = lt >> 5, b = lt & 31, Jj = J0 + jl;
            const float* p = psmL1 + b * 8;
            float4 a0 = *(const float4*)(p + (jl) * PSR);
            float4 a1 = *(const float4*)(p + (jl) * PSR + 4);
            float4 f0 = *(const float4*)(p + (4 + jl) * PSR);
            float4 f1 = *(const float4*)(p + (4 + jl) * PSR + 4);
            float4 g0 = *(const float4*)(p + (8 + jl) * PSR);
            float4 g1 = *(const float4*)(p + (8 + jl) * PSR + 4);
            float4 o0 = *(const float4*)(p + (12 + jl) * PSR);
            float4 o1 = *(const float4*)(p + (12 + jl) * PSR + 4);
            float gI = bsm[16 + jl]      + a0.x + a0.y + a0.z + a0.w + a1.x + a1.y + a1.z + a1.w;
            float gF = bsm[16 + 4 + jl]  + f0.x + f0.y + f0.z + f0.w + f1.x + f1.y + f1.z + f1.w;
            float gG = bsm[16 + 8 + jl]  + g0.x + g0.y + g0.z + g0.w + g1.x + g1.y + g1.z + g1.w;
            float gO = bsm[16 + 12 + jl] + o0.x + o0.y + o0.z + o0.w + o1.x + o1.y + o1.z + o1.w;
            float iv = sigf(gI), fv = sigf(gF), gv = tanhfast(gG), ov = sigf(gO);
            float c = fv * csm[128 + jl * 32 + b] + iv * gv;
            csm[128 + jl * 32 + b] = c;
            float h = ov * tanhfast(c);
            g_h1buf[(q0 << 14) + (b << 9) + Jj] = h;
            int t1 = v - 1;
            dout[((size_t)t1 << 14) + (b << 9) + Jj] = h;
            if (v == TT) {
                dout[OUT1_ELEMS + BH + (b << 9) + Jj] = h;
                dout[OUT1_ELEMS + 2 * BH + BH + (b << 9) + Jj] = c;
            }
        }

        flagbar(gbase + v + 2, tid);
    }
}

// ============================== launcher =====================================
extern "C" void kernel_launch(void* const* d_in, const int* in_sizes, int n_in,
                              void* d_out, int out_size) {
    const float* x     = (const float*)d_in[0];
    const float* w_ih0 = (const float*)d_in[1];
    const float* w_hh0 = (const float*)d_in[2];
    const float* b_ih0 = (const float*)d_in[3];
    const float* b_hh0 = (const float*)d_in[4];
    const float* w_ih1 = (const float*)d_in[5];
    const float* w_hh1 = (const float*)d_in[6];
    const float* b_ih1 = (const float*)d_in[7];
    const float* b_hh1 = (const float*)d_in[8];
    const float* h0    = (const float*)d_in[9];
    const float* c0    = (const float*)d_in[10];
    float* out = (float*)d_out;

    const int smem_bytes = 55968 * 4;  // 223872 B
    cudaFuncSetAttribute(lstm_rec, cudaFuncAttributeMaxDynamicSharedMemorySize,
                         smem_bytes);

    gemm_in2h<<<dim3(16, 256), 256>>>(x, w_ih0, b_ih0);
    lstm_rec<<<NBLK, 1024, smem_bytes>>>(w_hh0, b_hh0, w_ih1, w_hh1, b_ih1, b_hh1,
                                         h0, c0, out);
}

// round 16
// speedup vs baseline: 1.1720x; 1.1720x over previous
#include <cuda_runtime.h>
#include <cstddef>

#define TT 1024
#define BB 32
#define NBLK 128
#define OUT1_ELEMS (TT*BB*512)
#define BH (BB*512)

#define WTS 20      // weight smem stride per k (16 rows + 4 pad)
#define HSS 516     // h smem row stride
#define PSS 132     // psm row stride: 32 batches * 4 kh + 4 pad

// ---------------- device globals (scratch; no allocation allowed) ------------
__device__ float g_gi0[(size_t)TT * BB * 2048];
__device__ float g_h0buf[2 * BH];
__device__ float g_h1buf[2 * BH];
__device__ unsigned g_flags[NBLK * 64];   // one 256B slot per block, monotonic gen

__device__ __forceinline__ unsigned long long fma2(unsigned long long a,
                                                   unsigned long long b,
                                                   unsigned long long c) {
    unsigned long long d;
    asm("fma.rn.f32x2 %0, %1, %2, %3;" : "=l"(d) : "l"(a), "l"(b), "l"(c));
    return d;
}
__device__ __forceinline__ unsigned long long addf2(unsigned long long a,
                                                    unsigned long long b) {
    unsigned long long d;
    asm("add.rn.f32x2 %0, %1, %2;" : "=l"(d) : "l"(a), "l"(b));
    return d;
}

// ======================= input-projection GEMM (FFMA2) =======================
// C[M=32768][N=2048] = A[M][512] * W[N][512]^T + bias  ->  g_gi0
__global__ void __launch_bounds__(256) gemm_in2h(
    const float* __restrict__ A, const float* __restrict__ W,
    const float* __restrict__ bias)
{
    __shared__ float As[8][132];
    __shared__ float Bs[8][132];
    const int tid = threadIdx.x;
    const int n0 = blockIdx.x * 128;
    const int m0 = blockIdx.y * 128;
    const int tx = tid & 15, ty = tid >> 4;
    const int lrow = tid >> 1, lk4 = (tid & 1) * 4;
    const float* Ab = A + (size_t)(m0 + lrow) * 512 + lk4;
    const float* Wb = W + (size_t)(n0 + lrow) * 512 + lk4;

    // acc2[i][jp] holds columns {2jp, 2jp+1} of row i as packed f32x2
    unsigned long long acc2[8][4];
#pragma unroll
    for (int i = 0; i < 8; i++)
#pragma unroll
        for (int j = 0; j < 4; j++) acc2[i][j] = 0ull;

    for (int k0 = 0; k0 < 512; k0 += 8) {
        float4 av = *(const float4*)(Ab + k0);
        float4 wv = *(const float4*)(Wb + k0);
        As[lk4 + 0][lrow] = av.x; As[lk4 + 1][lrow] = av.y;
        As[lk4 + 2][lrow] = av.z; As[lk4 + 3][lrow] = av.w;
        Bs[lk4 + 0][lrow] = wv.x; Bs[lk4 + 1][lrow] = wv.y;
        Bs[lk4 + 2][lrow] = wv.z; Bs[lk4 + 3][lrow] = wv.w;
        __syncthreads();
#pragma unroll
        for (int k = 0; k < 8; k++) {
            float a[8];
            *(float4*)&a[0] = *(const float4*)&As[k][ty * 8];
            *(float4*)&a[4] = *(const float4*)&As[k][ty * 8 + 4];
            // b columns as 4 packed f32x2 (pairs are adjacent in Bs)
            ulonglong2 b01 = *(const ulonglong2*)&Bs[k][tx * 8];
            ulonglong2 b23 = *(const ulonglong2*)&Bs[k][tx * 8 + 4];
            unsigned long long bp[4] = {b01.x, b01.y, b23.x, b23.y};
#pragma unroll
            for (int i = 0; i < 8; i++) {
                unsigned long long Ai;
                asm("mov.b64 %0, {%1, %1};" : "=l"(Ai) : "f"(a[i]));
#pragma unroll
                for (int j = 0; j < 4; j++)
                    acc2[i][j] = fma2(Ai, bp[j], acc2[i][j]);
            }
        }
        __syncthreads();
    }

    float bv[8];
#pragma unroll
    for (int j = 0; j < 8; j++) bv[j] = bias[n0 + tx * 8 + j];
#pragma unroll
    for (int i = 0; i < 8; i++) {
        size_t row = (size_t)(m0 + ty * 8 + i);
        float* Crow = g_gi0 + row * 2048 + n0 + tx * 8;
#pragma unroll
        for (int j = 0; j < 4; j++) {
            float2 f = *(float2*)&acc2[i][j];
            Crow[2 * j]     = f.x + bv[2 * j];
            Crow[2 * j + 1] = f.y + bv[2 * j + 1];
        }
    }
}

// ======================= persistent recurrence kernel ========================
__device__ __forceinline__ float sigf(float x) {
    float e = __expf(fminf(-x, 80.f));
    return __fdividef(1.f, 1.f + e);
}
__device__ __forceinline__ float tanhfast(float x) {
    float e = __expf(fminf(2.f * x, 80.f));
    return 1.f - __fdividef(2.f, e + 1.f);
}

// distributed-flag barrier: per-block 256B slot, monotonic generation
__device__ __forceinline__ void flagbar(unsigned gen, int tid) {
    __syncthreads();
    if (tid == 0) {
        __threadfence();
        *(volatile unsigned*)&g_flags[blockIdx.x * 64] = gen;
    }
    if (tid < NBLK) {
        volatile unsigned* f = &g_flags[tid * 64];
        while (*f < gen) { }
    }
    __threadfence();
    __syncthreads();
}

// plain copy: src [32][512] contiguous -> hs rows of stride HSS
__device__ __forceinline__ void stage_h(float* __restrict__ hs,
                                        const float* __restrict__ src, int tid) {
#pragma unroll
    for (int it = 0; it < 8; it++) {
        int u4 = tid + it * 512;
        int b = u4 >> 7, k4 = (u4 & 127) << 2;
        *(float4*)(hs + b * HSS + k4) = ((const float4*)src)[u4];
    }
}

// warp covers: 2 batches (per thread) x 16 rows (8 f32x2 row-pairs) x 128 k
__device__ __forceinline__ void gemm_rp(const float* __restrict__ hs,
                                        const float* __restrict__ wt,
                                        int hbase, int kbase,
                                        unsigned long long acc[2][8]) {
    const float* hp = hs + hbase + kbase;
    const float* wp = wt + kbase * WTS;
#pragma unroll 4
    for (int m = 0; m < 16; m++) {
        float h0 = hp[m * 8];
        float h1 = hp[HSS + m * 8];
        unsigned long long H0, H1;
        asm("mov.b64 %0, {%1, %1};" : "=l"(H0) : "f"(h0));
        asm("mov.b64 %0, {%1, %1};" : "=l"(H1) : "f"(h1));
        const float* w = wp + m * 8 * WTS;
        ulonglong2 w01 = *(const ulonglong2*)(w);
        ulonglong2 w23 = *(const ulonglong2*)(w + 4);
        ulonglong2 w45 = *(const ulonglong2*)(w + 8);
        ulonglong2 w67 = *(const ulonglong2*)(w + 12);
        acc[0][0] = fma2(H0, w01.x, acc[0][0]); acc[1][0] = fma2(H1, w01.x, acc[1][0]);
        acc[0][1] = fma2(H0, w01.y, acc[0][1]); acc[1][1] = fma2(H1, w01.y, acc[1][1]);
        acc[0][2] = fma2(H0, w23.x, acc[0][2]); acc[1][2] = fma2(H1, w23.x, acc[1][2]);
        acc[0][3] = fma2(H0, w23.y, acc[0][3]); acc[1][3] = fma2(H1, w23.y, acc[1][3]);
        acc[0][4] = fma2(H0, w45.x, acc[0][4]); acc[1][4] = fma2(H1, w45.x, acc[1][4]);
        acc[0][5] = fma2(H0, w45.y, acc[0][5]); acc[1][5] = fma2(H1, w45.y, acc[1][5]);
        acc[0][6] = fma2(H0, w67.x, acc[0][6]); acc[1][6] = fma2(H1, w67.x, acc[1][6]);
        acc[0][7] = fma2(H0, w67.y, acc[0][7]); acc[1][7] = fma2(H1, w67.y, acc[1][7]);
    }
}

// reduce over the 8 kcl lanes; lane kcl writes row-pair j2 == kcl to psm[r][b][kh]
__device__ __forceinline__ void red_write_rp(unsigned long long acc[2][8],
                                             float* __restrict__ psm,
                                             int kh, int kcl, int b0t) {
#pragma unroll
    for (int j2 = 0; j2 < 8; j2++) {
#pragma unroll
        for (int b2 = 0; b2 < 2; b2++) {
            unsigned long long v = acc[b2][j2];
            v = addf2(v, __shfl_xor_sync(0xffffffffu, v, 1));
            v = addf2(v, __shfl_xor_sync(0xffffffffu, v, 2));
            v = addf2(v, __shfl_xor_sync(0xffffffffu, v, 4));
            acc[b2][j2] = v;
        }
        if (j2 == kcl) {
            float2 f0 = *(float2*)&acc[0][j2];
            float2 f1 = *(float2*)&acc[1][j2];
            psm[(2 * j2) * PSS     + b0t * 4       + kh] = f0.x;
            psm[(2 * j2 + 1) * PSS + b0t * 4       + kh] = f0.y;
            psm[(2 * j2) * PSS     + (b0t + 1) * 4 + kh] = f1.x;
            psm[(2 * j2 + 1) * PSS + (b0t + 1) * 4 + kh] = f1.y;
        }
    }
}

__global__ void __launch_bounds__(512, 1) lstm_rec(
    const float* __restrict__ w_hh0, const float* __restrict__ b_hh0,
    const float* __restrict__ w_ih1, const float* __restrict__ w_hh1,
    const float* __restrict__ b_ih1, const float* __restrict__ b_hh1,
    const float* __restrict__ h0_in, const float* __restrict__ c0_in,
    float* __restrict__ dout)
{
    extern __shared__ float sm[];
    float* ws0t  = sm;                    // 512*20 = 10240
    float* wsi1t = sm + 10240;
    float* wsh1t = sm + 20480;
    float* hs    = sm + 30720;            // 32*516 = 16512
    float* psmL0 = sm + 47232;            // 16*132 = 2112
    float* psmL1 = sm + 49344;            // 2112
    float* csm   = sm + 51456;            // 256

    const int tid = threadIdx.x;
    const int bid = blockIdx.x;
    const int J0 = bid << 2;

    const unsigned gbase = *(volatile unsigned*)&g_flags[bid * 64];

    // Stage 16 weight rows per matrix, k-major [k][16 + pad], once.
    for (int u = tid; u < 16 * 512; u += 512) {
        int r = u >> 9, k = u & 511;
        int gr = ((r >> 2) << 9) + J0 + (r & 3);
        int d = k * WTS + r;
        ws0t[d]  = w_hh0[gr * 512 + k];
        wsi1t[d] = w_ih1[gr * 512 + k];
        wsh1t[d] = w_hh1[gr * 512 + k];
    }
    // init hidden buffers at parity 1
    {
        int g = (bid << 9) + tid;
        if (g < BH)          g_h0buf[BH + g] = h0_in[g];
        else if (g < 2 * BH) g_h1buf[g]      = h0_in[g];
    }
    if (tid < 256) {
        int l = tid >> 7, jl = (tid >> 5) & 3, b = tid & 31;
        csm[tid] = c0_in[(l << 14) + (b << 9) + J0 + jl];
    }

    const int lane = tid & 31, warp = tid >> 5;
    const int bgrp = warp & 3, kh = warp >> 2;
    const int kcl = lane & 7, bsub = lane >> 3;
    const int b0t = bgrp * 8 + bsub * 2;
    const int kbase = kh * 128 + kcl;
    const int hbase = b0t * HSS;

    float bI0 = 0, bF0 = 0, bG0 = 0, bO0 = 0;
    float bI1 = 0, bF1 = 0, bG1 = 0, bO1 = 0;
    if (tid < 128) {
        int jl = tid >> 5, Jj = J0 + jl;
        bI0 = b_hh0[Jj];        bF0 = b_hh0[512 + Jj];
        bG0 = b_hh0[1024 + Jj]; bO0 = b_hh0[1536 + Jj];
    } else if (tid < 256) {
        int jl = (tid - 128) >> 5, Jj = J0 + jl;
        bI1 = b_ih1[Jj] + b_hh1[Jj];
        bF1 = b_ih1[512 + Jj] + b_hh1[512 + Jj];
        bG1 = b_ih1[1024 + Jj] + b_hh1[1024 + Jj];
        bO1 = b_ih1[1536 + Jj] + b_hh1[1536 + Jj];
    }

    flagbar(gbase + 1, tid);

    unsigned long long acc[2][8];

    // pipelined: interval v computes L0 step t0=v and L1 step t1=v-1
    for (int v = 0; v <= TT; v++) {
        const int p0 = v & 1, q0 = p0 ^ 1;

        float giI = 0, giF = 0, giG = 0, giO = 0;
        if (v < TT && tid < 128) {
            int jl = tid >> 5, b = tid & 31, Jj = J0 + jl;
            const float* gi = g_gi0 + ((size_t)v << 16) + ((size_t)b << 11);
            giI = gi[Jj]; giF = gi[512 + Jj]; giG = gi[1024 + Jj]; giO = gi[1536 + Jj];
        }

        // ---- shared h0(v-1) staging (used by L0 w_hh0 and L1 w_ih1) ----
        stage_h(hs, g_h0buf + (q0 << 14), tid);
        __syncthreads();

        if (v < TT) {
#pragma unroll
            for (int b2 = 0; b2 < 2; b2++)
#pragma unroll
                for (int j2 = 0; j2 < 8; j2++) acc[b2][j2] = 0ull;
            gemm_rp(hs, ws0t, hbase, kbase, acc);
            red_write_rp(acc, psmL0, kh, kcl, b0t);
        }
        if (v > 0) {
#pragma unroll
            for (int b2 = 0; b2 < 2; b2++)
#pragma unroll
                for (int j2 = 0; j2 < 8; j2++) acc[b2][j2] = 0ull;
            gemm_rp(hs, wsi1t, hbase, kbase, acc);
        }
        __syncthreads();   // done reading hs

        if (v > 0) {
            stage_h(hs, g_h1buf + (p0 << 14), tid);  // h1(v-2)
            __syncthreads();
            gemm_rp(hs, wsh1t, hbase, kbase, acc);   // accumulate
            red_write_rp(acc, psmL1, kh, kcl, b0t);
        }
        __syncthreads();   // psm ready

        // ---- L0 elementwise: step v ----
        if (v < TT && tid < 128) {
            int jl = tid >> 5, b = tid & 31, Jj = J0 + jl;
            float4 vI = *(const float4*)(psmL0 + (jl) * PSS + b * 4);
            float4 vF = *(const float4*)(psmL0 + (4 + jl) * PSS + b * 4);
            float4 vG = *(const float4*)(psmL0 + (8 + jl) * PSS + b * 4);
            float4 vO = *(const float4*)(psmL0 + (12 + jl) * PSS + b * 4);
            float gI = giI + bI0 + vI.x + vI.y + vI.z + vI.w;
            float gF = giF + bF0 + vF.x + vF.y + vF.z + vF.w;
            float gG = giG + bG0 + vG.x + vG.y + vG.z + vG.w;
            float gO = giO + bO0 + vO.x + vO.y + vO.z + vO.w;
            float iv = sigf(gI), fv = sigf(gF), gv = tanhfast(gG), ov = sigf(gO);
            float c = fv * csm[jl * 32 + b] + iv * gv;
            csm[jl * 32 + b] = c;
            float h = ov * tanhfast(c);
            g_h0buf[(p0 << 14) + (b << 9) + Jj] = h;
            if (v == TT - 1) {
                dout[OUT1_ELEMS + (b << 9) + Jj] = h;
                dout[OUT1_ELEMS + 2 * BH + (b << 9) + Jj] = c;
            }
        }

        // ---- L1 elementwise: step v-1 ----
        if (v > 0 && tid >= 128 && tid < 256) {
            int lt = tid - 128;
            int jl = lt >> 5, b = lt & 31, Jj = J0 + jl;
            float4 vI = *(const float4*)(psmL1 + (jl) * PSS + b * 4);
            float4 vF = *(const float4*)(psmL1 + (4 + jl) * PSS + b * 4);
            float4 vG = *(const float4*)(psmL1 + (8 + jl) * PSS + b * 4);
            float4 vO = *(const float4*)(psmL1 + (12 + jl) * PSS + b * 4);
            float gI = bI1 + vI.x + vI.y + vI.z + vI.w;
            float gF = bF1 + vF.x + vF.y + vF.z + vF.w;
            float gG = bG1 + vG.x + vG.y + vG.z + vG.w;
            float gO = bO1 + vO.x + vO.y + vO.z + vO.w;
            float iv = sigf(gI), fv = sigf(gF), gv = tanhfast(gG), ov = sigf(gO);
            float c = fv * csm[128 + jl * 32 + b] + iv * gv;
            csm[128 + jl * 32 + b] = c;
            float h = ov * tanhfast(c);
            g_h1buf[(q0 << 14) + (b << 9) + Jj] = h;
            int t1 = v - 1;
            dout[((size_t)t1 << 14) + (b << 9) + Jj] = h;
            if (v == TT) {
                dout[OUT1_ELEMS + BH + (b << 9) + Jj] = h;
                dout[OUT1_ELEMS + 2 * BH + BH + (b << 9) + Jj] = c;
            }
        }

        flagbar(gbase + v + 2, tid);
    }
}

// ============================== launcher =====================================
extern "C" void kernel_launch(void* const* d_in, const int* in_sizes, int n_in,
                              void* d_out, int out_size) {
    const float* x     = (const float*)d_in[0];
    const float* w_ih0 = (const float*)d_in[1];
    const float* w_hh0 = (const float*)d_in[2];
    const float* b_ih0 = (const float*)d_in[3];
    const float* b_hh0 = (const float*)d_in[4];
    const float* w_ih1 = (const float*)d_in[5];
    const float* w_hh1 = (const float*)d_in[6];
    const float* b_ih1 = (const float*)d_in[7];
    const float* b_hh1 = (const float*)d_in[8];
    const float* h0    = (const float*)d_in[9];
    const float* c0    = (const float*)d_in[10];
    float* out = (float*)d_out;

    const int smem_bytes = 51712 * 4;  // 206848 B
    cudaFuncSetAttribute(lstm_rec, cudaFuncAttributeMaxDynamicSharedMemorySize,
                         smem_bytes);

    gemm_in2h<<<dim3(16, 256), 256>>>(x, w_ih0, b_ih0);
    lstm_rec<<<NBLK, 512, smem_bytes>>>(w_hh0, b_hh0, w_ih1, w_hh1, b_ih1, b_hh1,
                                        h0, c0, out);
}